// round 2
// baseline (speedup 1.0000x reference)
#include <cuda_runtime.h>
#include <cstdint>

#define D 256            // D_IN == D_OUT == 256
#define MAX_NODES 100000

// Scratch for h = x@W + b  (102.4 MB device global; allocation-free rule)
__device__ float g_h[(size_t)MAX_NODES * D];

// ---------------------------------------------------------------------------
// Zero the output (harness poisons it with 0xAA)
// ---------------------------------------------------------------------------
__global__ void zero_kernel(float4* __restrict__ out, size_t n4) {
    size_t i = (size_t)blockIdx.x * blockDim.x + threadIdx.x;
    size_t stride = (size_t)gridDim.x * blockDim.x;
    for (; i < n4; i += stride)
        out[i] = make_float4(0.f, 0.f, 0.f, 0.f);
}

// ---------------------------------------------------------------------------
// GEMM + bias: H[M,256] = A[M,256] @ W[256,256] + bias
// 128x128 block tile, 16 K-tile, 8x8 per thread, 256 threads.
// ---------------------------------------------------------------------------
#define BM 128
#define BN 128
#define BK 16

__global__ __launch_bounds__(256) void gemm_bias_kernel(
    const float* __restrict__ A, const float* __restrict__ W,
    const float* __restrict__ bias, int M)
{
    __shared__ float As[BK][BM];   // transposed A tile: As[k][m]
    __shared__ float Bs[BK][BN];   // Bs[k][n]

    const int tid = threadIdx.x;
    const int tx = tid & 15;       // 0..15 (col group)
    const int ty = tid >> 4;       // 0..15 (row group)
    const int rowBase = blockIdx.x * BM;
    const int colBase = blockIdx.y * BN;

    float acc[8][8];
#pragma unroll
    for (int i = 0; i < 8; i++)
#pragma unroll
        for (int j = 0; j < 8; j++) acc[i][j] = 0.f;

    for (int k0 = 0; k0 < D; k0 += BK) {
        // Load A tile: 128 rows x 16 cols = 512 float4, 2 per thread.
#pragma unroll
        for (int i = 0; i < 2; i++) {
            int f  = tid + i * 256;
            int r  = f >> 2;              // row within tile (0..127)
            int kc = (f & 3) * 4;         // k within tile (float4 start)
            float4 v = make_float4(0.f, 0.f, 0.f, 0.f);
            int gr = rowBase + r;
            if (gr < M)
                v = *reinterpret_cast<const float4*>(A + (size_t)gr * D + k0 + kc);
            As[kc + 0][r] = v.x;
            As[kc + 1][r] = v.y;
            As[kc + 2][r] = v.z;
            As[kc + 3][r] = v.w;
        }
        // Load B tile: 16 rows x 128 cols = 512 float4, 2 per thread.
#pragma unroll
        for (int i = 0; i < 2; i++) {
            int f = tid + i * 256;
            int r = f >> 5;               // k row within tile (0..15)
            int c = (f & 31) * 4;         // col within tile
            float4 v = *reinterpret_cast<const float4*>(
                W + (size_t)(k0 + r) * D + colBase + c);
            *reinterpret_cast<float4*>(&Bs[r][c]) = v;
        }
        __syncthreads();

#pragma unroll
        for (int k = 0; k < BK; k++) {
            float a[8], b[8];
            *reinterpret_cast<float4*>(a)     = *reinterpret_cast<const float4*>(&As[k][ty * 8]);
            *reinterpret_cast<float4*>(a + 4) = *reinterpret_cast<const float4*>(&As[k][ty * 8 + 4]);
            *reinterpret_cast<float4*>(b)     = *reinterpret_cast<const float4*>(&Bs[k][tx * 8]);
            *reinterpret_cast<float4*>(b + 4) = *reinterpret_cast<const float4*>(&Bs[k][tx * 8 + 4]);
#pragma unroll
            for (int i = 0; i < 8; i++)
#pragma unroll
                for (int j = 0; j < 8; j++)
                    acc[i][j] += a[i] * b[j];
        }
        __syncthreads();
    }

    // Epilogue: add bias, store to g_h with float4 stores.
    float4 b0 = *reinterpret_cast<const float4*>(bias + colBase + tx * 8);
    float4 b1 = *reinterpret_cast<const float4*>(bias + colBase + tx * 8 + 4);
#pragma unroll
    for (int i = 0; i < 8; i++) {
        int gr = rowBase + ty * 8 + i;
        if (gr < M) {
            float* hp = g_h + (size_t)gr * D + colBase + tx * 8;
            float4 v0 = make_float4(acc[i][0] + b0.x, acc[i][1] + b0.y,
                                    acc[i][2] + b0.z, acc[i][3] + b0.w);
            float4 v1 = make_float4(acc[i][4] + b1.x, acc[i][5] + b1.y,
                                    acc[i][6] + b1.z, acc[i][7] + b1.w);
            *reinterpret_cast<float4*>(hp)     = v0;
            *reinterpret_cast<float4*>(hp + 4) = v1;
        }
    }
}

// ---------------------------------------------------------------------------
// Scatter: out[dst] += val * h[src]   (one warp per edge)
// Each lane handles 2 float4 (8 floats) of the 256-wide row.
// Uses red.global.add.v4.f32 (no-return vector reduction, sm_90+).
// ---------------------------------------------------------------------------
__global__ __launch_bounds__(512) void scatter_kernel(
    const int* __restrict__ esrc, const int* __restrict__ edst,
    const float* __restrict__ eval, float* __restrict__ out, int E)
{
    int gw   = (int)(((size_t)blockIdx.x * blockDim.x + threadIdx.x) >> 5);
    int lane = threadIdx.x & 31;
    if (gw >= E) return;

    int   s = __ldg(esrc + gw);   // broadcast within warp (single sector)
    int   d = __ldg(edst + gw);
    float v = __ldg(eval + gw);

    const float4* hr = reinterpret_cast<const float4*>(g_h + (size_t)s * D);
    float4 a = __ldg(hr + lane);
    float4 b = __ldg(hr + lane + 32);

    float* o = out + (size_t)d * D;
    asm volatile("red.global.add.v4.f32 [%0], {%1,%2,%3,%4};" ::
                 "l"(o + lane * 4),
                 "f"(a.x * v), "f"(a.y * v), "f"(a.z * v), "f"(a.w * v)
                 : "memory");
    asm volatile("red.global.add.v4.f32 [%0], {%1,%2,%3,%4};" ::
                 "l"(o + 128 + lane * 4),
                 "f"(b.x * v), "f"(b.y * v), "f"(b.z * v), "f"(b.w * v)
                 : "memory");
}

// ---------------------------------------------------------------------------
extern "C" void kernel_launch(void* const* d_in, const int* in_sizes, int n_in,
                              void* d_out, int out_size)
{
    const float* x    = (const float*)d_in[0];
    const float* w    = (const float*)d_in[1];
    const float* bias = (const float*)d_in[2];
    const int*   esrc = (const int*)d_in[3];
    const int*   edst = (const int*)d_in[4];
    const float* eval = (const float*)d_in[5];
    float*       out  = (float*)d_out;

    const int M = in_sizes[0] / D;     // 100000
    const int E = in_sizes[3];         // 3200000

    // 1) zero output
    size_t n4 = (size_t)out_size / 4;
    if (n4) zero_kernel<<<2048, 256>>>((float4*)d_out, n4);

    // 2) h = x @ W + b  -> g_h
    if (M > 0) {
        dim3 ggrid((M + BM - 1) / BM, D / BN);
        gemm_bias_kernel<<<ggrid, 256>>>(x, w, bias, M);
    }

    // 3) out[dst] += val * h[src]
    if (E > 0) {
        long long warps  = (long long)E;
        long long blocks = (warps * 32 + 511) / 512;
        scatter_kernel<<<(unsigned int)blocks, 512>>>(esrc, edst, eval, out, E);
    }
}

// round 4
// speedup vs baseline: 2.1423x; 2.1423x over previous
#include <cuda_runtime.h>
#include <cuda_fp16.h>
#include <cstdint>

#define D 256            // D_IN == D_OUT == 256
#define MAX_NODES 100000
#define MAX_EDGES 3200000

// -------- device scratch (allocation-free rule) ----------------------------
__device__ __half g_h[(size_t)MAX_NODES * D];          // 51.2 MB  h = xW+b (fp16)
__device__ int    g_cnt[MAX_NODES];                    // per-dst degree
__device__ int    g_rowptr[MAX_NODES + 1];             // CSR row pointers
__device__ int    g_cursor[MAX_NODES];                 // fill cursors
__device__ int    g_partials[256];                     // scan block partials
__device__ int    g_ssrc[MAX_EDGES];                   // edges sorted by dst: src
__device__ float  g_sval[MAX_EDGES];                   // edges sorted by dst: val

// ---------------------------------------------------------------------------
// GEMM + bias: h[M,256] = x[M,256] @ W[256,256] + bias   (fp32 math, fp16 out)
// ---------------------------------------------------------------------------
#define BM 128
#define BN 128
#define BK 16

__global__ __launch_bounds__(256) void gemm_bias_kernel(
    const float* __restrict__ A, const float* __restrict__ W,
    const float* __restrict__ bias, int M)
{
    __shared__ float As[BK][BM];   // transposed A tile: As[k][m]
    __shared__ float Bs[BK][BN];   // Bs[k][n]

    const int tid = threadIdx.x;
    const int tx = tid & 15;       // 0..15 (col group)
    const int ty = tid >> 4;       // 0..15 (row group)
    const int rowBase = blockIdx.x * BM;
    const int colBase = blockIdx.y * BN;

    float acc[8][8];
#pragma unroll
    for (int i = 0; i < 8; i++)
#pragma unroll
        for (int j = 0; j < 8; j++) acc[i][j] = 0.f;

    for (int k0 = 0; k0 < D; k0 += BK) {
#pragma unroll
        for (int i = 0; i < 2; i++) {
            int f  = tid + i * 256;
            int r  = f >> 2;
            int kc = (f & 3) * 4;
            float4 v = make_float4(0.f, 0.f, 0.f, 0.f);
            int gr = rowBase + r;
            if (gr < M)
                v = *reinterpret_cast<const float4*>(A + (size_t)gr * D + k0 + kc);
            As[kc + 0][r] = v.x;
            As[kc + 1][r] = v.y;
            As[kc + 2][r] = v.z;
            As[kc + 3][r] = v.w;
        }
#pragma unroll
        for (int i = 0; i < 2; i++) {
            int f = tid + i * 256;
            int r = f >> 5;
            int c = (f & 31) * 4;
            float4 v = *reinterpret_cast<const float4*>(
                W + (size_t)(k0 + r) * D + colBase + c);
            *reinterpret_cast<float4*>(&Bs[r][c]) = v;
        }
        __syncthreads();

#pragma unroll
        for (int k = 0; k < BK; k++) {
            float a[8], b[8];
            *reinterpret_cast<float4*>(a)     = *reinterpret_cast<const float4*>(&As[k][ty * 8]);
            *reinterpret_cast<float4*>(a + 4) = *reinterpret_cast<const float4*>(&As[k][ty * 8 + 4]);
            *reinterpret_cast<float4*>(b)     = *reinterpret_cast<const float4*>(&Bs[k][tx * 8]);
            *reinterpret_cast<float4*>(b + 4) = *reinterpret_cast<const float4*>(&Bs[k][tx * 8 + 4]);
#pragma unroll
            for (int i = 0; i < 8; i++)
#pragma unroll
                for (int j = 0; j < 8; j++)
                    acc[i][j] += a[i] * b[j];
        }
        __syncthreads();
    }

    float4 b0 = *reinterpret_cast<const float4*>(bias + colBase + tx * 8);
    float4 b1 = *reinterpret_cast<const float4*>(bias + colBase + tx * 8 + 4);
#pragma unroll
    for (int i = 0; i < 8; i++) {
        int gr = rowBase + ty * 8 + i;
        if (gr < M) {
            __half* hp = g_h + (size_t)gr * D + colBase + tx * 8;
            __half2 p0 = __floats2half2_rn(acc[i][0] + b0.x, acc[i][1] + b0.y);
            __half2 p1 = __floats2half2_rn(acc[i][2] + b0.z, acc[i][3] + b0.w);
            __half2 p2 = __floats2half2_rn(acc[i][4] + b1.x, acc[i][5] + b1.y);
            __half2 p3 = __floats2half2_rn(acc[i][6] + b1.z, acc[i][7] + b1.w);
            uint4 pk;
            pk.x = *reinterpret_cast<uint32_t*>(&p0);
            pk.y = *reinterpret_cast<uint32_t*>(&p1);
            pk.z = *reinterpret_cast<uint32_t*>(&p2);
            pk.w = *reinterpret_cast<uint32_t*>(&p3);
            *reinterpret_cast<uint4*>(hp) = pk;
        }
    }
}

// ---------------------------------------------------------------------------
// CSR build
// ---------------------------------------------------------------------------
__global__ void zero_cnt_kernel(int N) {
    int i = blockIdx.x * blockDim.x + threadIdx.x;
    if (i < N) g_cnt[i] = 0;
}

__global__ void hist_kernel(const int* __restrict__ edst, int E) {
    int stride = gridDim.x * blockDim.x;
    for (int e = blockIdx.x * blockDim.x + threadIdx.x; e < E; e += stride)
        atomicAdd(&g_cnt[edst[e]], 1);
}

// block-level exclusive scan of g_cnt into g_rowptr, block totals -> g_partials
__global__ __launch_bounds__(1024) void scan_blocks_kernel(int N) {
    __shared__ int s[1024];
    int t = threadIdx.x;
    int i = blockIdx.x * 1024 + t;
    int v = (i < N) ? g_cnt[i] : 0;
    s[t] = v;
    __syncthreads();
    for (int off = 1; off < 1024; off <<= 1) {
        int add = (t >= off) ? s[t - off] : 0;
        __syncthreads();
        s[t] += add;
        __syncthreads();
    }
    if (i < N) g_rowptr[i] = s[t] - v;               // exclusive, block-local
    if (t == 1023) g_partials[blockIdx.x] = s[t];    // block total
}

// exclusive scan of the (<=256) block partials, in place
__global__ __launch_bounds__(256) void scan_partials_kernel(int NB) {
    __shared__ int s[256];
    int t = threadIdx.x;
    int v = (t < NB) ? g_partials[t] : 0;
    s[t] = v;
    __syncthreads();
    for (int off = 1; off < 256; off <<= 1) {
        int add = (t >= off) ? s[t - off] : 0;
        __syncthreads();
        s[t] += add;
        __syncthreads();
    }
    if (t < NB) g_partials[t] = s[t] - v;            // exclusive
}

__global__ void finalize_rowptr_kernel(int N, int E) {
    int i = blockIdx.x * blockDim.x + threadIdx.x;
    if (i < N) {
        int v = g_rowptr[i] + g_partials[i >> 10];
        g_rowptr[i] = v;
        g_cursor[i] = v;
    }
    if (i == 0) g_rowptr[N] = E;
}

__global__ void fill_kernel(const int* __restrict__ esrc,
                            const int* __restrict__ edst,
                            const float* __restrict__ eval, int E)
{
    int stride = gridDim.x * blockDim.x;
    for (int e = blockIdx.x * blockDim.x + threadIdx.x; e < E; e += stride) {
        int d = edst[e];
        int pos = atomicAdd(&g_cursor[d], 1);
        g_ssrc[pos] = esrc[e];
        g_sval[pos] = eval[e];
    }
}

// ---------------------------------------------------------------------------
// Gather: one warp per dst node. acc[8] fp32 per lane; h rows read as fp16.
// Writes out exactly once per node (no atomics, covers degree-0 with zeros).
// ---------------------------------------------------------------------------
__global__ __launch_bounds__(256) void gather_kernel(float* __restrict__ out, int N)
{
    int node = (int)(((size_t)blockIdx.x * blockDim.x + threadIdx.x) >> 5);
    int lane = threadIdx.x & 31;
    if (node >= N) return;

    int start = __ldg(&g_rowptr[node]);
    int end   = __ldg(&g_rowptr[node + 1]);

    float acc[8];
#pragma unroll
    for (int i = 0; i < 8; i++) acc[i] = 0.f;

    for (int e = start; e < end; e += 32) {
        int cnt = min(32, end - e);
        int   sl = (lane < cnt) ? __ldg(&g_ssrc[e + lane]) : 0;
        float vl = (lane < cnt) ? __ldg(&g_sval[e + lane]) : 0.f;

        for (int j = 0; j < cnt; j++) {
            int   s = __shfl_sync(0xffffffffu, sl, j);
            float v = __shfl_sync(0xffffffffu, vl, j);
            const uint4* hr = reinterpret_cast<const uint4*>(g_h + (size_t)s * D);
            uint4 u = __ldg(hr + lane);
            __half2 h0 = *reinterpret_cast<__half2*>(&u.x);
            __half2 h1 = *reinterpret_cast<__half2*>(&u.y);
            __half2 h2 = *reinterpret_cast<__half2*>(&u.z);
            __half2 h3 = *reinterpret_cast<__half2*>(&u.w);
            float2 f0 = __half22float2(h0);
            float2 f1 = __half22float2(h1);
            float2 f2 = __half22float2(h2);
            float2 f3 = __half22float2(h3);
            acc[0] += v * f0.x; acc[1] += v * f0.y;
            acc[2] += v * f1.x; acc[3] += v * f1.y;
            acc[4] += v * f2.x; acc[5] += v * f2.y;
            acc[6] += v * f3.x; acc[7] += v * f3.y;
        }
    }

    float* o = out + (size_t)node * D + lane * 8;
    *reinterpret_cast<float4*>(o)     = make_float4(acc[0], acc[1], acc[2], acc[3]);
    *reinterpret_cast<float4*>(o + 4) = make_float4(acc[4], acc[5], acc[6], acc[7]);
}

// ---------------------------------------------------------------------------
extern "C" void kernel_launch(void* const* d_in, const int* in_sizes, int n_in,
                              void* d_out, int out_size)
{
    const float* x    = (const float*)d_in[0];
    const float* w    = (const float*)d_in[1];
    const float* bias = (const float*)d_in[2];
    const int*   esrc = (const int*)d_in[3];
    const int*   edst = (const int*)d_in[4];
    const float* eval = (const float*)d_in[5];
    float*       out  = (float*)d_out;

    const int M = in_sizes[0] / D;     // 100000 (rows of x)
    const int E = in_sizes[3];         // 3200000
    const int N = out_size / D;        // 100000 (dst nodes)
    const int NB = (N + 1023) / 1024;  // scan blocks (<=256)

    // 1) h = x @ W + b  (fp16 out)
    if (M > 0) {
        dim3 ggrid((M + BM - 1) / BM, D / BN);
        gemm_bias_kernel<<<ggrid, 256>>>(x, w, bias, M);
    }

    // 2) build CSR by dst
    zero_cnt_kernel<<<(N + 255) / 256, 256>>>(N);
    if (E > 0) hist_kernel<<<4096, 256>>>(edst, E);
    scan_blocks_kernel<<<NB, 1024>>>(N);
    scan_partials_kernel<<<1, 256>>>(NB);
    finalize_rowptr_kernel<<<(N + 255) / 256, 256>>>(N, E);
    if (E > 0) fill_kernel<<<4096, 256>>>(esrc, edst, eval, E);

    // 3) out[n] = sum_{e: dst=n} val_e * h[src_e]
    long long threads = (long long)N * 32;
    gather_kernel<<<(unsigned int)((threads + 255) / 256), 256>>>(out, N);
}

// round 5
// speedup vs baseline: 4.1512x; 1.9378x over previous
#include <cuda_runtime.h>
#include <cuda_fp16.h>
#include <cstdint>

#define D 256            // D_IN == D_OUT == 256
#define MAX_NODES 100000
#define MAX_EDGES 3200000

// -------- device scratch (allocation-free rule) ----------------------------
__device__ __half g_h[(size_t)MAX_NODES * D];   // 51.2 MB  h = xW+b (fp16)
__device__ __half g_wh[D * D];                  // W in fp16
__device__ int    g_cnt[MAX_NODES];             // per-dst degree
__device__ int    g_rowptr[MAX_NODES + 1];      // CSR row pointers
__device__ int    g_cursor[MAX_NODES];          // fill cursors
__device__ int    g_partials[256];              // scan block partials
__device__ int2   g_edge[MAX_EDGES];            // sorted by dst: (src, val bits)

// ---------------------------------------------------------------------------
__global__ void convert_w_kernel(const float* __restrict__ W) {
    int i = blockIdx.x * blockDim.x + threadIdx.x;   // D*D/2 threads
    float2 v = reinterpret_cast<const float2*>(W)[i];
    reinterpret_cast<__half2*>(g_wh)[i] = __floats2half2_rn(v.x, v.y);
}

// ---------------------------------------------------------------------------
// Tensor-core GEMM + bias: h[M,256] = x[M,256] @ W[256,256] + b  (fp16 out)
// 128x128 block tile, K-tile 32, 8 warps (4m x 2n), warp tile 32x64,
// mma.sync.m16n8k16 f32<-f16*f16.
// ---------------------------------------------------------------------------
#define GBM 128
#define GBK 32
#define LDA 40    // halves, conflict-free for ldmatrix
#define LDB 136   // halves, conflict-free for ldmatrix

__device__ __forceinline__ uint32_t smem_u32(const void* p) {
    return (uint32_t)__cvta_generic_to_shared(p);
}

__global__ __launch_bounds__(256) void hgemm_kernel(
    const float* __restrict__ X, const float* __restrict__ bias, int M)
{
    __shared__ __half As[GBM][LDA];   // 128 x 32 (+pad)
    __shared__ __half Bs[GBK][LDB];   // 32 x 128 (+pad)

    const int tid  = threadIdx.x;
    const int lane = tid & 31;
    const int warp = tid >> 5;
    const int wm   = warp & 3;        // 0..3  -> m offset wm*32
    const int wn   = warp >> 2;       // 0..1  -> n offset wn*64
    const int rowBase = blockIdx.x * GBM;
    const int colBase = blockIdx.y * 128;

    float acc[2][8][4];
#pragma unroll
    for (int mt = 0; mt < 2; mt++)
#pragma unroll
        for (int nt = 0; nt < 8; nt++)
#pragma unroll
            for (int q = 0; q < 4; q++) acc[mt][nt][q] = 0.f;

    for (int kt = 0; kt < D; kt += GBK) {
        // ---- load A tile: 128 rows x 32 fp32 -> fp16  (1024 float4, 4/thread)
#pragma unroll
        for (int i = 0; i < 4; i++) {
            int f  = tid + i * 256;
            int r  = f >> 3;            // 0..127
            int c4 = f & 7;             // float4 index within row
            int gr = rowBase + r;
            float4 v = make_float4(0.f, 0.f, 0.f, 0.f);
            if (gr < M)
                v = *reinterpret_cast<const float4*>(X + (size_t)gr * D + kt + c4 * 4);
            __half2 h0 = __floats2half2_rn(v.x, v.y);
            __half2 h1 = __floats2half2_rn(v.z, v.w);
            uint2 pk;
            pk.x = *reinterpret_cast<uint32_t*>(&h0);
            pk.y = *reinterpret_cast<uint32_t*>(&h1);
            *reinterpret_cast<uint2*>(&As[r][c4 * 4]) = pk;
        }
        // ---- load B tile: 32 rows x 128 fp16  (512 uint4, 2/thread)
#pragma unroll
        for (int i = 0; i < 2; i++) {
            int f  = tid + i * 256;
            int r  = f >> 4;            // 0..31
            int c8 = f & 15;            // uint4 index within row
            uint4 v = *reinterpret_cast<const uint4*>(
                g_wh + (size_t)(kt + r) * D + colBase + c8 * 8);
            *reinterpret_cast<uint4*>(&Bs[r][c8 * 8]) = v;
        }
        __syncthreads();

#pragma unroll
        for (int ks = 0; ks < 2; ks++) {
            uint32_t a[2][4], b[4][4];
#pragma unroll
            for (int mt = 0; mt < 2; mt++) {
                uint32_t addr = smem_u32(
                    &As[wm * 32 + mt * 16 + (lane & 15)][ks * 16 + (lane >> 4) * 8]);
                asm volatile(
                    "ldmatrix.sync.aligned.m8n8.x4.shared.b16 {%0,%1,%2,%3}, [%4];"
                    : "=r"(a[mt][0]), "=r"(a[mt][1]), "=r"(a[mt][2]), "=r"(a[mt][3])
                    : "r"(addr));
            }
#pragma unroll
            for (int p = 0; p < 4; p++) {   // covers n-tiles 2p, 2p+1
                uint32_t addr = smem_u32(
                    &Bs[ks * 16 + (lane & 15)][wn * 64 + p * 16 + (lane >> 4) * 8]);
                asm volatile(
                    "ldmatrix.sync.aligned.m8n8.x4.trans.shared.b16 {%0,%1,%2,%3}, [%4];"
                    : "=r"(b[p][0]), "=r"(b[p][1]), "=r"(b[p][2]), "=r"(b[p][3])
                    : "r"(addr));
            }
#pragma unroll
            for (int mt = 0; mt < 2; mt++)
#pragma unroll
                for (int nt = 0; nt < 8; nt++) {
                    int p = nt >> 1, q = (nt & 1) * 2;
                    asm volatile(
                        "mma.sync.aligned.m16n8k16.row.col.f32.f16.f16.f32 "
                        "{%0,%1,%2,%3}, {%4,%5,%6,%7}, {%8,%9}, {%0,%1,%2,%3};"
                        : "+f"(acc[mt][nt][0]), "+f"(acc[mt][nt][1]),
                          "+f"(acc[mt][nt][2]), "+f"(acc[mt][nt][3])
                        : "r"(a[mt][0]), "r"(a[mt][1]), "r"(a[mt][2]), "r"(a[mt][3]),
                          "r"(b[p][q]), "r"(b[p][q + 1]));
                }
        }
        __syncthreads();
    }

    // ---- epilogue: + bias, fp16 store
#pragma unroll
    for (int mt = 0; mt < 2; mt++)
#pragma unroll
        for (int nt = 0; nt < 8; nt++) {
            int gr0 = rowBase + wm * 32 + mt * 16 + (lane >> 2);
            int gc  = colBase + wn * 64 + nt * 8 + (lane & 3) * 2;
            float2 bv = *reinterpret_cast<const float2*>(bias + gc);
            if (gr0 < M) {
                __half2 o = __floats2half2_rn(acc[mt][nt][0] + bv.x,
                                              acc[mt][nt][1] + bv.y);
                *reinterpret_cast<__half2*>(g_h + (size_t)gr0 * D + gc) = o;
            }
            int gr1 = gr0 + 8;
            if (gr1 < M) {
                __half2 o = __floats2half2_rn(acc[mt][nt][2] + bv.x,
                                              acc[mt][nt][3] + bv.y);
                *reinterpret_cast<__half2*>(g_h + (size_t)gr1 * D + gc) = o;
            }
        }
}

// ---------------------------------------------------------------------------
// CSR build
// ---------------------------------------------------------------------------
__global__ void zero_cnt_kernel(int N) {
    int i = blockIdx.x * blockDim.x + threadIdx.x;
    if (i < N) g_cnt[i] = 0;
}

__global__ void hist_kernel(const int* __restrict__ edst, int E) {
    int stride = gridDim.x * blockDim.x;
    for (int e = blockIdx.x * blockDim.x + threadIdx.x; e < E; e += stride)
        atomicAdd(&g_cnt[edst[e]], 1);
}

__global__ __launch_bounds__(1024) void scan_blocks_kernel(int N) {
    __shared__ int s[1024];
    int t = threadIdx.x;
    int i = blockIdx.x * 1024 + t;
    int v = (i < N) ? g_cnt[i] : 0;
    s[t] = v;
    __syncthreads();
    for (int off = 1; off < 1024; off <<= 1) {
        int add = (t >= off) ? s[t - off] : 0;
        __syncthreads();
        s[t] += add;
        __syncthreads();
    }
    if (i < N) g_rowptr[i] = s[t] - v;
    if (t == 1023) g_partials[blockIdx.x] = s[t];
}

__global__ __launch_bounds__(256) void scan_partials_kernel(int NB) {
    __shared__ int s[256];
    int t = threadIdx.x;
    int v = (t < NB) ? g_partials[t] : 0;
    s[t] = v;
    __syncthreads();
    for (int off = 1; off < 256; off <<= 1) {
        int add = (t >= off) ? s[t - off] : 0;
        __syncthreads();
        s[t] += add;
        __syncthreads();
    }
    if (t < NB) g_partials[t] = s[t] - v;
}

__global__ void finalize_rowptr_kernel(int N, int E) {
    int i = blockIdx.x * blockDim.x + threadIdx.x;
    if (i < N) {
        int v = g_rowptr[i] + g_partials[i >> 10];
        g_rowptr[i] = v;
        g_cursor[i] = v;
    }
    if (i == 0) g_rowptr[N] = E;
}

__global__ void fill_kernel(const int* __restrict__ esrc,
                            const int* __restrict__ edst,
                            const float* __restrict__ eval, int E)
{
    int stride = gridDim.x * blockDim.x;
    for (int e = blockIdx.x * blockDim.x + threadIdx.x; e < E; e += stride) {
        int d = edst[e];
        int pos = atomicAdd(&g_cursor[d], 1);
        g_edge[pos] = make_int2(esrc[e], __float_as_int(eval[e]));
    }
}

// ---------------------------------------------------------------------------
// Gather: one warp per dst node; fp32 acc; single exact write per node.
// ---------------------------------------------------------------------------
__global__ __launch_bounds__(256) void gather_kernel(float* __restrict__ out, int N)
{
    int node = (int)(((size_t)blockIdx.x * blockDim.x + threadIdx.x) >> 5);
    int lane = threadIdx.x & 31;
    if (node >= N) return;

    int start = __ldg(&g_rowptr[node]);
    int end   = __ldg(&g_rowptr[node + 1]);

    float acc[8];
#pragma unroll
    for (int i = 0; i < 8; i++) acc[i] = 0.f;

    for (int e = start; e < end; e += 32) {
        int cnt = min(32, end - e);
        int2 ev = (lane < cnt) ? __ldg(&g_edge[e + lane]) : make_int2(0, 0);

        for (int j = 0; j < cnt; j++) {
            int   s = __shfl_sync(0xffffffffu, ev.x, j);
            float v = __int_as_float(__shfl_sync(0xffffffffu, ev.y, j));
            const uint4* hr = reinterpret_cast<const uint4*>(g_h + (size_t)s * D);
            uint4 u = __ldg(hr + lane);
            __half2 h0 = *reinterpret_cast<__half2*>(&u.x);
            __half2 h1 = *reinterpret_cast<__half2*>(&u.y);
            __half2 h2 = *reinterpret_cast<__half2*>(&u.z);
            __half2 h3 = *reinterpret_cast<__half2*>(&u.w);
            float2 f0 = __half22float2(h0);
            float2 f1 = __half22float2(h1);
            float2 f2 = __half22float2(h2);
            float2 f3 = __half22float2(h3);
            acc[0] += v * f0.x; acc[1] += v * f0.y;
            acc[2] += v * f1.x; acc[3] += v * f1.y;
            acc[4] += v * f2.x; acc[5] += v * f2.y;
            acc[6] += v * f3.x; acc[7] += v * f3.y;
        }
    }

    float* o = out + (size_t)node * D + lane * 8;
    *reinterpret_cast<float4*>(o)     = make_float4(acc[0], acc[1], acc[2], acc[3]);
    *reinterpret_cast<float4*>(o + 4) = make_float4(acc[4], acc[5], acc[6], acc[7]);
}

// ---------------------------------------------------------------------------
extern "C" void kernel_launch(void* const* d_in, const int* in_sizes, int n_in,
                              void* d_out, int out_size)
{
    const float* x    = (const float*)d_in[0];
    const float* w    = (const float*)d_in[1];
    const float* bias = (const float*)d_in[2];
    const int*   esrc = (const int*)d_in[3];
    const int*   edst = (const int*)d_in[4];
    const float* eval = (const float*)d_in[5];
    float*       out  = (float*)d_out;

    const int M = in_sizes[0] / D;     // 100000 (rows of x)
    const int E = in_sizes[3];         // 3200000
    const int N = out_size / D;        // 100000 (dst nodes)
    const int NB = (N + 1023) / 1024;  // scan blocks (<=256)

    // 1) W -> fp16, then h = x @ W + b (tensor cores, fp16 out)
    convert_w_kernel<<<D * D / 2 / 256, 256>>>(w);
    if (M > 0) {
        dim3 ggrid((M + GBM - 1) / GBM, 2);
        hgemm_kernel<<<ggrid, 256>>>(x, bias, M);
    }

    // 2) build CSR by dst
    zero_cnt_kernel<<<(N + 255) / 256, 256>>>(N);
    if (E > 0) hist_kernel<<<4096, 256>>>(edst, E);
    scan_blocks_kernel<<<NB, 1024>>>(N);
    scan_partials_kernel<<<1, 256>>>(NB);
    finalize_rowptr_kernel<<<(N + 255) / 256, 256>>>(N, E);
    if (E > 0) fill_kernel<<<4096, 256>>>(esrc, edst, eval, E);

    // 3) out[n] = sum_{e: dst=n} val_e * h[src_e]
    long long threads = (long long)N * 32;
    gather_kernel<<<(unsigned int)((threads + 255) / 256), 256>>>(out, N);
}

// round 6
// speedup vs baseline: 4.3365x; 1.0446x over previous
#include <cuda_runtime.h>
#include <cuda_fp16.h>
#include <cstdint>

#define D 256            // D_IN == D_OUT == 256
#define MAX_NODES 100000
#define MAX_EDGES 3200000

// -------- device scratch (allocation-free rule) ----------------------------
__device__ __half g_h[(size_t)MAX_NODES * D];   // 51.2 MB  h = xW+b (fp16)
__device__ __half g_wh[D * D];                  // W in fp16
__device__ int    g_cnt[MAX_NODES];             // per-dst degree
__device__ int    g_rowptr[MAX_NODES + 1];      // CSR row pointers
__device__ int    g_cursor[MAX_NODES];          // fill cursors
__device__ int    g_partials[256];              // scan block partials
__device__ int2   g_edge[MAX_EDGES];            // sorted by dst: (src, val bits)

// ---------------------------------------------------------------------------
__global__ void convert_w_kernel(const float* __restrict__ W) {
    int i = blockIdx.x * blockDim.x + threadIdx.x;   // D*D/2 threads
    float2 v = reinterpret_cast<const float2*>(W)[i];
    reinterpret_cast<__half2*>(g_wh)[i] = __floats2half2_rn(v.x, v.y);
}

// ---------------------------------------------------------------------------
// Tensor-core GEMM + bias: h[M,256] = x[M,256] @ W[256,256] + b  (fp16 out)
// 128x128 block tile, K-tile 32, 8 warps (4m x 2n), warp tile 32x64,
// mma.sync.m16n8k16 f32<-f16*f16.
// ---------------------------------------------------------------------------
#define GBM 128
#define GBK 32
#define LDA 40    // halves, conflict-free for ldmatrix
#define LDB 136   // halves, conflict-free for ldmatrix

__device__ __forceinline__ uint32_t smem_u32(const void* p) {
    return (uint32_t)__cvta_generic_to_shared(p);
}

__global__ __launch_bounds__(256) void hgemm_kernel(
    const float* __restrict__ X, const float* __restrict__ bias, int M)
{
    __shared__ __half As[GBM][LDA];   // 128 x 32 (+pad)
    __shared__ __half Bs[GBK][LDB];   // 32 x 128 (+pad)

    const int tid  = threadIdx.x;
    const int lane = tid & 31;
    const int warp = tid >> 5;
    const int wm   = warp & 3;        // 0..3  -> m offset wm*32
    const int wn   = warp >> 2;       // 0..1  -> n offset wn*64
    const int rowBase = blockIdx.x * GBM;
    const int colBase = blockIdx.y * 128;

    float acc[2][8][4];
#pragma unroll
    for (int mt = 0; mt < 2; mt++)
#pragma unroll
        for (int nt = 0; nt < 8; nt++)
#pragma unroll
            for (int q = 0; q < 4; q++) acc[mt][nt][q] = 0.f;

    for (int kt = 0; kt < D; kt += GBK) {
        // ---- load A tile: 128 rows x 32 fp32 -> fp16  (1024 float4, 4/thread)
#pragma unroll
        for (int i = 0; i < 4; i++) {
            int f  = tid + i * 256;
            int r  = f >> 3;            // 0..127
            int c4 = f & 7;             // float4 index within row
            int gr = rowBase + r;
            float4 v = make_float4(0.f, 0.f, 0.f, 0.f);
            if (gr < M)
                v = *reinterpret_cast<const float4*>(X + (size_t)gr * D + kt + c4 * 4);
            __half2 h0 = __floats2half2_rn(v.x, v.y);
            __half2 h1 = __floats2half2_rn(v.z, v.w);
            uint2 pk;
            pk.x = *reinterpret_cast<uint32_t*>(&h0);
            pk.y = *reinterpret_cast<uint32_t*>(&h1);
            *reinterpret_cast<uint2*>(&As[r][c4 * 4]) = pk;
        }
        // ---- load B tile: 32 rows x 128 fp16  (512 uint4, 2/thread)
#pragma unroll
        for (int i = 0; i < 2; i++) {
            int f  = tid + i * 256;
            int r  = f >> 4;            // 0..31
            int c8 = f & 15;            // uint4 index within row
            uint4 v = *reinterpret_cast<const uint4*>(
                g_wh + (size_t)(kt + r) * D + colBase + c8 * 8);
            *reinterpret_cast<uint4*>(&Bs[r][c8 * 8]) = v;
        }
        __syncthreads();

#pragma unroll
        for (int ks = 0; ks < 2; ks++) {
            uint32_t a[2][4], b[4][4];
#pragma unroll
            for (int mt = 0; mt < 2; mt++) {
                uint32_t addr = smem_u32(
                    &As[wm * 32 + mt * 16 + (lane & 15)][ks * 16 + (lane >> 4) * 8]);
                asm volatile(
                    "ldmatrix.sync.aligned.m8n8.x4.shared.b16 {%0,%1,%2,%3}, [%4];"
                    : "=r"(a[mt][0]), "=r"(a[mt][1]), "=r"(a[mt][2]), "=r"(a[mt][3])
                    : "r"(addr));
            }
#pragma unroll
            for (int p = 0; p < 4; p++) {   // covers n-tiles 2p, 2p+1
                uint32_t addr = smem_u32(
                    &Bs[ks * 16 + (lane & 15)][wn * 64 + p * 16 + (lane >> 4) * 8]);
                asm volatile(
                    "ldmatrix.sync.aligned.m8n8.x4.trans.shared.b16 {%0,%1,%2,%3}, [%4];"
                    : "=r"(b[p][0]), "=r"(b[p][1]), "=r"(b[p][2]), "=r"(b[p][3])
                    : "r"(addr));
            }
#pragma unroll
            for (int mt = 0; mt < 2; mt++)
#pragma unroll
                for (int nt = 0; nt < 8; nt++) {
                    int p = nt >> 1, q = (nt & 1) * 2;
                    asm volatile(
                        "mma.sync.aligned.m16n8k16.row.col.f32.f16.f16.f32 "
                        "{%0,%1,%2,%3}, {%4,%5,%6,%7}, {%8,%9}, {%0,%1,%2,%3};"
                        : "+f"(acc[mt][nt][0]), "+f"(acc[mt][nt][1]),
                          "+f"(acc[mt][nt][2]), "+f"(acc[mt][nt][3])
                        : "r"(a[mt][0]), "r"(a[mt][1]), "r"(a[mt][2]), "r"(a[mt][3]),
                          "r"(b[p][q]), "r"(b[p][q + 1]));
                }
        }
        __syncthreads();
    }

    // ---- epilogue: + bias, fp16 store
#pragma unroll
    for (int mt = 0; mt < 2; mt++)
#pragma unroll
        for (int nt = 0; nt < 8; nt++) {
            int gr0 = rowBase + wm * 32 + mt * 16 + (lane >> 2);
            int gc  = colBase + wn * 64 + nt * 8 + (lane & 3) * 2;
            float2 bv = *reinterpret_cast<const float2*>(bias + gc);
            if (gr0 < M) {
                __half2 o = __floats2half2_rn(acc[mt][nt][0] + bv.x,
                                              acc[mt][nt][1] + bv.y);
                *reinterpret_cast<__half2*>(g_h + (size_t)gr0 * D + gc) = o;
            }
            int gr1 = gr0 + 8;
            if (gr1 < M) {
                __half2 o = __floats2half2_rn(acc[mt][nt][2] + bv.x,
                                              acc[mt][nt][3] + bv.y);
                *reinterpret_cast<__half2*>(g_h + (size_t)gr1 * D + gc) = o;
            }
        }
}

// ---------------------------------------------------------------------------
// CSR build
// ---------------------------------------------------------------------------
__global__ void zero_cnt_kernel(int N) {
    int i = blockIdx.x * blockDim.x + threadIdx.x;
    if (i < N) g_cnt[i] = 0;
}

__global__ void hist_kernel(const int* __restrict__ edst, int E) {
    int stride = gridDim.x * blockDim.x;
    for (int e = blockIdx.x * blockDim.x + threadIdx.x; e < E; e += stride)
        atomicAdd(&g_cnt[__ldcs(edst + e)], 1);
}

__global__ __launch_bounds__(1024) void scan_blocks_kernel(int N) {
    __shared__ int s[1024];
    int t = threadIdx.x;
    int i = blockIdx.x * 1024 + t;
    int v = (i < N) ? g_cnt[i] : 0;
    s[t] = v;
    __syncthreads();
    for (int off = 1; off < 1024; off <<= 1) {
        int add = (t >= off) ? s[t - off] : 0;
        __syncthreads();
        s[t] += add;
        __syncthreads();
    }
    if (i < N) g_rowptr[i] = s[t] - v;
    if (t == 1023) g_partials[blockIdx.x] = s[t];
}

__global__ __launch_bounds__(256) void scan_partials_kernel(int NB) {
    __shared__ int s[256];
    int t = threadIdx.x;
    int v = (t < NB) ? g_partials[t] : 0;
    s[t] = v;
    __syncthreads();
    for (int off = 1; off < 256; off <<= 1) {
        int add = (t >= off) ? s[t - off] : 0;
        __syncthreads();
        s[t] += add;
        __syncthreads();
    }
    if (t < NB) g_partials[t] = s[t] - v;
}

__global__ void finalize_rowptr_kernel(int N, int E) {
    int i = blockIdx.x * blockDim.x + threadIdx.x;
    if (i < N) {
        int v = g_rowptr[i] + g_partials[i >> 10];
        g_rowptr[i] = v;
        g_cursor[i] = v;
    }
    if (i == 0) g_rowptr[N] = E;
}

__global__ void fill_kernel(const int* __restrict__ esrc,
                            const int* __restrict__ edst,
                            const float* __restrict__ eval, int E)
{
    int stride = gridDim.x * blockDim.x;
    for (int e = blockIdx.x * blockDim.x + threadIdx.x; e < E; e += stride) {
        int d = __ldcs(edst + e);
        int s = __ldcs(esrc + e);
        float v = __ldcs(eval + e);
        int pos = atomicAdd(&g_cursor[d], 1);
        __stcs(&g_edge[pos], make_int2(s, __float_as_int(v)));
    }
}

// ---------------------------------------------------------------------------
// Gather: one warp per dst node; fp32 acc; single exact write per node.
// out stores use .cs so the 102MB write stream doesn't evict h from L2.
// ---------------------------------------------------------------------------
__global__ __launch_bounds__(256) void gather_kernel(float* __restrict__ out, int N)
{
    int node = (int)(((size_t)blockIdx.x * blockDim.x + threadIdx.x) >> 5);
    int lane = threadIdx.x & 31;
    if (node >= N) return;

    int start = __ldg(&g_rowptr[node]);
    int end   = __ldg(&g_rowptr[node + 1]);

    float acc[8];
#pragma unroll
    for (int i = 0; i < 8; i++) acc[i] = 0.f;

    for (int e = start; e < end; e += 32) {
        int cnt = min(32, end - e);
        int2 ev = (lane < cnt) ? __ldcs(&g_edge[e + lane]) : make_int2(0, 0);

        for (int j = 0; j < cnt; j++) {
            int   s = __shfl_sync(0xffffffffu, ev.x, j);
            float v = __int_as_float(__shfl_sync(0xffffffffu, ev.y, j));
            const uint4* hr = reinterpret_cast<const uint4*>(g_h + (size_t)s * D);
            uint4 u = __ldg(hr + lane);
            __half2 h0 = *reinterpret_cast<__half2*>(&u.x);
            __half2 h1 = *reinterpret_cast<__half2*>(&u.y);
            __half2 h2 = *reinterpret_cast<__half2*>(&u.z);
            __half2 h3 = *reinterpret_cast<__half2*>(&u.w);
            float2 f0 = __half22float2(h0);
            float2 f1 = __half22float2(h1);
            float2 f2 = __half22float2(h2);
            float2 f3 = __half22float2(h3);
            acc[0] += v * f0.x; acc[1] += v * f0.y;
            acc[2] += v * f1.x; acc[3] += v * f1.y;
            acc[4] += v * f2.x; acc[5] += v * f2.y;
            acc[6] += v * f3.x; acc[7] += v * f3.y;
        }
    }

    float* o = out + (size_t)node * D + lane * 8;
    __stcs(reinterpret_cast<float4*>(o),     make_float4(acc[0], acc[1], acc[2], acc[3]));
    __stcs(reinterpret_cast<float4*>(o + 4), make_float4(acc[4], acc[5], acc[6], acc[7]));
}

// ---------------------------------------------------------------------------
extern "C" void kernel_launch(void* const* d_in, const int* in_sizes, int n_in,
                              void* d_out, int out_size)
{
    const float* x    = (const float*)d_in[0];
    const float* w    = (const float*)d_in[1];
    const float* bias = (const float*)d_in[2];
    const int*   esrc = (const int*)d_in[3];
    const int*   edst = (const int*)d_in[4];
    const float* eval = (const float*)d_in[5];
    float*       out  = (float*)d_out;

    const int M = in_sizes[0] / D;     // 100000 (rows of x)
    const int E = in_sizes[3];         // 3200000
    const int N = out_size / D;        // 100000 (dst nodes)
    const int NB = (N + 1023) / 1024;  // scan blocks (<=256)

    // Fork a second branch for the CSR build (independent of the GEMM).
    // Created fresh each call: no static guards, no device memory.
    cudaStream_t sB = 0;
    cudaEvent_t evFork = 0, evJoin = 0;
    bool forked = (cudaStreamCreateWithFlags(&sB, cudaStreamNonBlocking) == cudaSuccess) &&
                  (cudaEventCreateWithFlags(&evFork, cudaEventDisableTiming) == cudaSuccess) &&
                  (cudaEventCreateWithFlags(&evJoin, cudaEventDisableTiming) == cudaSuccess);

    cudaStream_t sCSR = 0;             // falls back to serial if fork failed
    if (forked) {
        cudaEventRecord(evFork, 0);
        cudaStreamWaitEvent(sB, evFork, 0);
        sCSR = sB;
    }

    // ---- branch A (stream 0): W -> fp16, h = x @ W + b
    convert_w_kernel<<<D * D / 2 / 256, 256>>>(w);
    if (M > 0) {
        dim3 ggrid((M + GBM - 1) / GBM, 2);
        hgemm_kernel<<<ggrid, 256>>>(x, bias, M);
    }

    // ---- branch B (sCSR): build CSR by dst
    zero_cnt_kernel<<<(N + 255) / 256, 256, 0, sCSR>>>(N);
    if (E > 0) hist_kernel<<<4096, 256, 0, sCSR>>>(edst, E);
    scan_blocks_kernel<<<NB, 1024, 0, sCSR>>>(N);
    scan_partials_kernel<<<1, 256, 0, sCSR>>>(NB);
    finalize_rowptr_kernel<<<(N + 255) / 256, 256, 0, sCSR>>>(N, E);
    if (E > 0) fill_kernel<<<4096, 256, 0, sCSR>>>(esrc, edst, eval, E);

    if (forked) {
        cudaEventRecord(evJoin, sB);
        cudaStreamWaitEvent(0, evJoin, 0);
    }

    // ---- join: out[n] = sum_{e: dst=n} val_e * h[src_e]
    long long threads = (long long)N * 32;
    gather_kernel<<<(unsigned int)((threads + 255) / 256), 256>>>(out, N);
}